// round 7
// baseline (speedup 1.0000x reference)
#include <cuda_runtime.h>
#include <cuda_fp16.h>
#include <math.h>
#include <stdint.h>

#define BB 8
#define NN 1024
#define CC 1024
#define HH 16
#define DD 64

// Scratch (allocation-free rule: __device__ globals)
__device__ __half g_q[BB * HH * NN * DD];
__device__ __half g_k[BB * HH * NN * DD];
__device__ __half g_v[BB * HH * NN * DD];
__device__ __half g_attn[BB * NN * CC];
__device__ __half g_x[BB * NN * CC];
__device__ __half g_wqkvT[3 * CC * CC];   // [n][k]
__device__ __half g_wprojT[CC * CC];      // [n][k]

__device__ __forceinline__ void mma16(float* d, const uint32_t* a, uint32_t b0,
                                      uint32_t b1) {
    asm volatile(
        "mma.sync.aligned.m16n8k16.row.col.f32.f16.f16.f32 "
        "{%0,%1,%2,%3}, {%4,%5,%6,%7}, {%8,%9}, {%0,%1,%2,%3};\n"
        : "+f"(d[0]), "+f"(d[1]), "+f"(d[2]), "+f"(d[3])
        : "r"(a[0]), "r"(a[1]), "r"(a[2]), "r"(a[3]), "r"(b0), "r"(b1));
}

__device__ __forceinline__ void ldm4(uint32_t* r, const __half* p) {
    uint32_t a = (uint32_t)__cvta_generic_to_shared(p);
    asm volatile(
        "ldmatrix.sync.aligned.m8n8.x4.shared.b16 {%0,%1,%2,%3}, [%4];\n"
        : "=r"(r[0]), "=r"(r[1]), "=r"(r[2]), "=r"(r[3])
        : "r"(a));
}
__device__ __forceinline__ void ldm4t(uint32_t* r, const __half* p) {
    uint32_t a = (uint32_t)__cvta_generic_to_shared(p);
    asm volatile(
        "ldmatrix.sync.aligned.m8n8.x4.trans.shared.b16 {%0,%1,%2,%3}, [%4];\n"
        : "=r"(r[0]), "=r"(r[1]), "=r"(r[2]), "=r"(r[3])
        : "r"(a));
}

__device__ __forceinline__ uint32_t packh2(float a, float b) {
    __half2 h = __floats2half2_rn(a, b);
    return *reinterpret_cast<uint32_t*>(&h);
}

__device__ __forceinline__ void cp16(__half* smem, const __half* gmem) {
    uint32_t s = (uint32_t)__cvta_generic_to_shared(smem);
    asm volatile("cp.async.cg.shared.global [%0], [%1], 16;\n" ::"r"(s), "l"(gmem)
                 : "memory");
}
__device__ __forceinline__ void cp_commit() {
    asm volatile("cp.async.commit_group;\n" ::: "memory");
}
template <int N>
__device__ __forceinline__ void cp_wait() {
    asm volatile("cp.async.wait_group %0;\n" ::"n"(N) : "memory");
}

// ---------------------------------------------------------------------------
// Pre-passes: f32 -> f16 conversion (x), transpose+convert (weights).
// ---------------------------------------------------------------------------
__global__ void conv_x(const float* __restrict__ in, __half* __restrict__ out) {
    int i = blockIdx.x * 256 + threadIdx.x;
    float4 v = ((const float4*)in)[i];
    ((__half2*)out)[2 * i] = __floats2half2_rn(v.x, v.y);
    ((__half2*)out)[2 * i + 1] = __floats2half2_rn(v.z, v.w);
}

__global__ void tconv(const float* __restrict__ in, __half* __restrict__ out,
                      int Ncols) {
    __shared__ float t[32][33];
    int n0 = blockIdx.x * 32, k0 = blockIdx.y * 32;
    int tx = threadIdx.x & 31, ty = threadIdx.x >> 5;
#pragma unroll
    for (int i = 0; i < 4; i++)
        t[ty + 8 * i][tx] = in[(size_t)(k0 + ty + 8 * i) * Ncols + n0 + tx];
    __syncthreads();
#pragma unroll
    for (int i = 0; i < 4; i++)
        out[(size_t)(n0 + ty + 8 * i) * 1024 + k0 + tx] =
            __float2half_rn(t[tx][ty + 8 * i]);
}

// ---------------------------------------------------------------------------
// fp16 mma.sync GEMM. 128x128 CTA tile, k-step 64, 3-stage cp.async ring.
// A [m][k], B [n][k] (pre-transposed). Stage layout [128][72] halves:
// ldmatrix rows stride 144B -> 9r mod 32 distinct -> conflict-free.
// MODE 0: Y = x @ w_qkv, fused RoPE -> g_q/g_k/g_v (f16).
// MODE 1: out = attn @ w_proj + bias (f32).
// ---------------------------------------------------------------------------
#define TSH 72
#define STG_H (128 * TSH)
#define GEMM_SMEM (3 * 2 * STG_H * 2)

template <int MODE>
__global__ __launch_bounds__(256, 2) void gemm_f16(const float* __restrict__ bias,
                                                   float* __restrict__ out) {
    extern __shared__ __half smh[];
    __half* As = smh;                // [3][128][72]
    __half* Bs = smh + 3 * STG_H;    // [3][128][72]

    const int tid = threadIdx.x;
    const int bx = blockIdx.x, by = blockIdx.y;
    const int lane = tid & 31, warp = tid >> 5;
    const int wm = warp & 3, wn = warp >> 2;
    const int r = lane >> 2, q = lane & 3;
    const int lrow = lane & 15, lcol = (lane >> 4) * 8;

    float acc[2][8][4];
#pragma unroll
    for (int mi = 0; mi < 2; mi++)
#pragma unroll
        for (int ni = 0; ni < 8; ni++)
#pragma unroll
            for (int c = 0; c < 4; c++) acc[mi][ni][c] = 0.f;

    const int srow = tid >> 1, shalf = (tid & 1) * 32;  // 4x16B per op per thread
    const __half* Ap = (MODE == 0) ? g_x : g_attn;
    const __half* Bp = (MODE == 0) ? g_wqkvT : g_wprojT;
    const __half* Ag = Ap + (size_t)(by * 128 + srow) * 1024 + shalf;
    const __half* Bg = Bp + (size_t)(bx * 128 + srow) * 1024 + shalf;

    auto load_stage = [&](int st, int k0) {
        __half* Ad = As + st * STG_H + srow * TSH + shalf;
        __half* Bd = Bs + st * STG_H + srow * TSH + shalf;
#pragma unroll
        for (int l = 0; l < 4; l++) {
            cp16(Ad + l * 8, Ag + k0 + l * 8);
            cp16(Bd + l * 8, Bg + k0 + l * 8);
        }
        cp_commit();
    };

    load_stage(0, 0);
    load_stage(1, 64);

    for (int it = 0; it < 16; it++) {
        if (it + 2 < 16) cp_wait<1>(); else cp_wait<0>();
        __syncthreads();
        if (it + 2 < 16) load_stage((it + 2) % 3, (it + 2) * 64);

        const __half* Ac = As + (it % 3) * STG_H;
        const __half* Bc = Bs + (it % 3) * STG_H;
#pragma unroll
        for (int ks = 0; ks < 4; ks++) {
            uint32_t af[2][4], bf[4][4];
#pragma unroll
            for (int mi = 0; mi < 2; mi++)
                ldm4(af[mi], &Ac[(wm * 32 + mi * 16 + lrow) * TSH + ks * 16 + lcol]);
#pragma unroll
            for (int nb = 0; nb < 4; nb++)
                ldm4(bf[nb], &Bc[(wn * 64 + nb * 16 + lrow) * TSH + ks * 16 + lcol]);
#pragma unroll
            for (int mi = 0; mi < 2; mi++)
#pragma unroll
                for (int nb = 0; nb < 4; nb++) {
                    mma16(acc[mi][2 * nb], af[mi], bf[nb][0], bf[nb][2]);
                    mma16(acc[mi][2 * nb + 1], af[mi], bf[nb][1], bf[nb][3]);
                }
        }
    }

    // Epilogue: C frag (mi,ni): rows r / r+8, cols ni*8 + 2q, 2q+1.
#pragma unroll
    for (int mi = 0; mi < 2; mi++)
#pragma unroll
        for (int ni = 0; ni < 8; ni++)
#pragma unroll
            for (int ch = 0; ch < 2; ch++) {
                int gr = by * 128 + wm * 32 + mi * 16 + ch * 8 + r;
                int gc = bx * 128 + wn * 64 + ni * 8 + 2 * q;
                float v1 = acc[mi][ni][ch * 2], v2 = acc[mi][ni][ch * 2 + 1];
                if (MODE == 1) {
                    float2 o = make_float2(v1 + bias[gc], v2 + bias[gc + 1]);
                    *(float2*)&out[(size_t)gr * 1024 + gc] = o;
                } else {
                    int b = gr >> 10, n = gr & 1023;
                    int which = gc >> 10, within = gc & 1023;
                    int h = within >> 6, d = within & 63;
                    size_t idx = (((size_t)(b * HH + h)) * NN + n) * DD + d;
                    if (which == 2) {
                        __half2 o = __floats2half2_rn(v1, v2);
                        *(__half2*)&g_v[idx] = o;
                    } else {
                        int p = d >> 1;
                        float omega = exp2f(-0.41524101186f * (float)p);
                        float ang = (float)n * omega;
                        float si, co;
                        sincosf(ang, &si, &co);
                        __half2 o = __floats2half2_rn(v1 * co - v2 * si,
                                                      v2 * co + v1 * si);
                        __half* dst = which ? g_k : g_q;
                        *(__half2*)&dst[idx] = o;
                    }
                }
            }
}

// ---------------------------------------------------------------------------
// fp16 mma.sync flash attention. CTA = 128 q-rows of one (b,h).
// Warp = 16 q-rows x all 64 keys; quad-local softmax sums; S-acc -> P A-frag
// in registers (no P smem). K: ldmatrix; V: ldmatrix.trans. 3-stage KV ring.
// ---------------------------------------------------------------------------
#define QS_H (128 * 72)
#define KV_H (64 * 72)
#define ATTN_SMEM ((QS_H + 6 * KV_H) * 2)

__global__ __launch_bounds__(256, 2) void attn_f16() {
    extern __shared__ __half smh[];
    __half* Qs = smh;
    __half* Ks = smh + QS_H;
    __half* Vs = smh + QS_H + 3 * KV_H;

    const int tid = threadIdx.x;
    const int lane = tid & 31, w = tid >> 5;
    const int r = lane >> 2, q = lane & 3;
    const int lrow = lane & 15, lcol = (lane >> 4) * 8;
    const int qt = blockIdx.x, h = blockIdx.y, b = blockIdx.z;

    const __half* Qg = g_q + ((size_t)(b * HH + h) * NN + qt * 128) * DD;
    const __half* Kg = g_k + (size_t)(b * HH + h) * NN * DD;
    const __half* Vg = g_v + (size_t)(b * HH + h) * NN * DD;

    auto load_kv = [&](int kt, int st) {
#pragma unroll
        for (int l = 0; l < 2; l++) {
            int c = tid + 256 * l;
            int row = c >> 3, ch = c & 7;
            cp16(&Ks[st * KV_H + row * 72 + ch * 8],
                 Kg + (size_t)(kt * 64 + row) * DD + ch * 8);
            cp16(&Vs[st * KV_H + row * 72 + ch * 8],
                 Vg + (size_t)(kt * 64 + row) * DD + ch * 8);
        }
        cp_commit();
    };

#pragma unroll
    for (int l = 0; l < 4; l++) {
        int c = tid + 256 * l;
        int row = c >> 3, ch = c & 7;
        cp16(&Qs[row * 72 + ch * 8], Qg + (size_t)row * DD + ch * 8);
    }
    load_kv(0, 0);
    load_kv(1, 1);

    uint32_t qf[4][4];
    float Oa[8][4];
#pragma unroll
    for (int ni = 0; ni < 8; ni++)
#pragma unroll
        for (int c = 0; c < 4; c++) Oa[ni][c] = 0.f;
    float lsum0 = 0.f, lsum1 = 0.f;

    for (int kt = 0; kt < 16; kt++) {
        cp_wait<1>();
        __syncthreads();
        if (kt == 0) {
#pragma unroll
            for (int j = 0; j < 4; j++)
                ldm4(qf[j], &Qs[(w * 16 + lrow) * 72 + j * 16 + lcol]);
        }
        if (kt + 2 < 16) load_kv(kt + 2, (kt + 2) % 3);

        const __half* Kc = Ks + (kt % 3) * KV_H;
        const __half* Vc = Vs + (kt % 3) * KV_H;

        float s[8][4];
#pragma unroll
        for (int ni = 0; ni < 8; ni++)
#pragma unroll
            for (int c = 0; c < 4; c++) s[ni][c] = 0.f;
#pragma unroll
        for (int j = 0; j < 4; j++) {
            uint32_t kf[4][4];
#pragma unroll
            for (int nb = 0; nb < 4; nb++)
                ldm4(kf[nb], &Kc[(nb * 16 + lrow) * 72 + j * 16 + lcol]);
#pragma unroll
            for (int nb = 0; nb < 4; nb++) {
                mma16(s[2 * nb], qf[j], kf[nb][0], kf[nb][2]);
                mma16(s[2 * nb + 1], qf[j], kf[nb][1], kf[nb][3]);
            }
        }

        float rs0 = 0.f, rs1 = 0.f;
#pragma unroll
        for (int j = 0; j < 4; j++) {
            float e00 = __expf(s[2 * j][0] * 0.125f);
            float e01 = __expf(s[2 * j][1] * 0.125f);
            float e02 = __expf(s[2 * j][2] * 0.125f);
            float e03 = __expf(s[2 * j][3] * 0.125f);
            float e10 = __expf(s[2 * j + 1][0] * 0.125f);
            float e11 = __expf(s[2 * j + 1][1] * 0.125f);
            float e12 = __expf(s[2 * j + 1][2] * 0.125f);
            float e13 = __expf(s[2 * j + 1][3] * 0.125f);
            rs0 += e00 + e01 + e10 + e11;
            rs1 += e02 + e03 + e12 + e13;
            uint32_t pa[4];
            pa[0] = packh2(e00, e01);
            pa[1] = packh2(e02, e03);
            pa[2] = packh2(e10, e11);
            pa[3] = packh2(e12, e13);

            uint32_t vf[4][4];
#pragma unroll
            for (int g = 0; g < 4; g++)
                ldm4t(vf[g], &Vc[(j * 16 + lrow) * 72 + g * 16 + lcol]);
#pragma unroll
            for (int g = 0; g < 4; g++) {
                mma16(Oa[2 * g], pa, vf[g][0], vf[g][1]);
                mma16(Oa[2 * g + 1], pa, vf[g][2], vf[g][3]);
            }
        }
        rs0 += __shfl_xor_sync(0xffffffffu, rs0, 1);
        rs0 += __shfl_xor_sync(0xffffffffu, rs0, 2);
        rs1 += __shfl_xor_sync(0xffffffffu, rs1, 1);
        rs1 += __shfl_xor_sync(0xffffffffu, rs1, 2);
        lsum0 += rs0;
        lsum1 += rs1;
        __syncthreads();
    }

    float inv0 = 1.f / lsum0, inv1 = 1.f / lsum1;
    int n0 = qt * 128 + w * 16 + r;
    size_t b0 = (((size_t)(b * NN + n0)) * HH + h) * DD;
    size_t b1 = (((size_t)(b * NN + n0 + 8)) * HH + h) * DD;
#pragma unroll
    for (int ni = 0; ni < 8; ni++) {
        *(__half2*)&g_attn[b0 + ni * 8 + 2 * q] =
            __floats2half2_rn(Oa[ni][0] * inv0, Oa[ni][1] * inv0);
        *(__half2*)&g_attn[b1 + ni * 8 + 2 * q] =
            __floats2half2_rn(Oa[ni][2] * inv1, Oa[ni][3] * inv1);
    }
}

extern "C" void kernel_launch(void* const* d_in, const int* in_sizes, int n_in,
                              void* d_out, int out_size) {
    const float* x = (const float*)d_in[0];
    const float* w_qkv = (const float*)d_in[1];
    const float* w_proj = (const float*)d_in[2];
    const float* b_proj = (const float*)d_in[3];
    float* out = (float*)d_out;

    cudaFuncSetAttribute(gemm_f16<0>, cudaFuncAttributeMaxDynamicSharedMemorySize,
                         GEMM_SMEM);
    cudaFuncSetAttribute(gemm_f16<1>, cudaFuncAttributeMaxDynamicSharedMemorySize,
                         GEMM_SMEM);
    cudaFuncSetAttribute(attn_f16, cudaFuncAttributeMaxDynamicSharedMemorySize,
                         ATTN_SMEM);

    __half* gx;  cudaGetSymbolAddress((void**)&gx, g_x);
    __half* gwq; cudaGetSymbolAddress((void**)&gwq, g_wqkvT);
    __half* gwp; cudaGetSymbolAddress((void**)&gwp, g_wprojT);

    conv_x<<<8192, 256>>>(x, gx);
    tconv<<<dim3(96, 32), 256>>>(w_qkv, gwq, 3072);
    tconv<<<dim3(32, 32), 256>>>(w_proj, gwp, 1024);

    gemm_f16<0><<<dim3(24, 64), 256, GEMM_SMEM>>>(nullptr, nullptr);
    attn_f16<<<dim3(8, 16, 8), 256, ATTN_SMEM>>>();
    gemm_f16<1><<<dim3(8, 64), 256, GEMM_SMEM>>>(b_proj, out);
}

// round 8
// speedup vs baseline: 1.1079x; 1.1079x over previous
#include <cuda_runtime.h>
#include <cuda_fp16.h>
#include <math.h>
#include <stdint.h>

#define BB 8
#define NN 1024
#define CC 1024
#define HH 16
#define DD 64

// Scratch (allocation-free rule: __device__ globals)
__device__ __half g_q[BB * HH * NN * DD];
__device__ __half g_k[BB * HH * NN * DD];
__device__ __half g_v[BB * HH * NN * DD];
__device__ __half g_attn[BB * NN * CC];
__device__ __half g_x[BB * NN * CC];
__device__ __half g_wqkvT[3 * CC * CC];   // [n][k]
__device__ __half g_wprojT[CC * CC];      // [n][k]

__device__ __forceinline__ void mma16(float* d, const uint32_t* a, uint32_t b0,
                                      uint32_t b1) {
    asm volatile(
        "mma.sync.aligned.m16n8k16.row.col.f32.f16.f16.f32 "
        "{%0,%1,%2,%3}, {%4,%5,%6,%7}, {%8,%9}, {%0,%1,%2,%3};\n"
        : "+f"(d[0]), "+f"(d[1]), "+f"(d[2]), "+f"(d[3])
        : "r"(a[0]), "r"(a[1]), "r"(a[2]), "r"(a[3]), "r"(b0), "r"(b1));
}

__device__ __forceinline__ void ldm4a(uint32_t* r, uint32_t a) {
    asm volatile(
        "ldmatrix.sync.aligned.m8n8.x4.shared.b16 {%0,%1,%2,%3}, [%4];\n"
        : "=r"(r[0]), "=r"(r[1]), "=r"(r[2]), "=r"(r[3])
        : "r"(a));
}
__device__ __forceinline__ void ldm4(uint32_t* r, const __half* p) {
    ldm4a(r, (uint32_t)__cvta_generic_to_shared(p));
}
__device__ __forceinline__ void ldm4t(uint32_t* r, const __half* p) {
    uint32_t a = (uint32_t)__cvta_generic_to_shared(p);
    asm volatile(
        "ldmatrix.sync.aligned.m8n8.x4.trans.shared.b16 {%0,%1,%2,%3}, [%4];\n"
        : "=r"(r[0]), "=r"(r[1]), "=r"(r[2]), "=r"(r[3])
        : "r"(a));
}

__device__ __forceinline__ uint32_t packh2(float a, float b) {
    __half2 h = __floats2half2_rn(a, b);
    return *reinterpret_cast<uint32_t*>(&h);
}

__device__ __forceinline__ void cp16(__half* smem, const __half* gmem) {
    uint32_t s = (uint32_t)__cvta_generic_to_shared(smem);
    asm volatile("cp.async.cg.shared.global [%0], [%1], 16;\n" ::"r"(s), "l"(gmem)
                 : "memory");
}
__device__ __forceinline__ void cp_commit() {
    asm volatile("cp.async.commit_group;\n" ::: "memory");
}
template <int N>
__device__ __forceinline__ void cp_wait() {
    asm volatile("cp.async.wait_group %0;\n" ::"n"(N) : "memory");
}

// ---------------------------------------------------------------------------
// Pre-passes: f32 -> f16 conversion (x), transpose+convert (weights).
// ---------------------------------------------------------------------------
__global__ void conv_x(const float* __restrict__ in, __half* __restrict__ out) {
    int i = blockIdx.x * 256 + threadIdx.x;
    float4 v = ((const float4*)in)[i];
    ((__half2*)out)[2 * i] = __floats2half2_rn(v.x, v.y);
    ((__half2*)out)[2 * i + 1] = __floats2half2_rn(v.z, v.w);
}

__global__ void tconv(const float* __restrict__ in, __half* __restrict__ out,
                      int Ncols) {
    __shared__ float t[32][33];
    int n0 = blockIdx.x * 32, k0 = blockIdx.y * 32;
    int tx = threadIdx.x & 31, ty = threadIdx.x >> 5;
#pragma unroll
    for (int i = 0; i < 4; i++)
        t[ty + 8 * i][tx] = in[(size_t)(k0 + ty + 8 * i) * Ncols + n0 + tx];
    __syncthreads();
#pragma unroll
    for (int i = 0; i < 4; i++)
        out[(size_t)(n0 + ty + 8 * i) * 1024 + k0 + tx] =
            __float2half_rn(t[tx][ty + 8 * i]);
}

// ---------------------------------------------------------------------------
// fp16 mma.sync GEMM. 128x128 CTA tile, k-step 32, 5-stage cp.async ring,
// register double-buffered fragments (LDSM for slice s+1 overlaps MMA of s).
// A [m][k], B [n][k] (pre-transposed). Stage [128][40] halves, conflict-free.
// MODE 0: Y = x @ w_qkv, fused RoPE -> g_q/g_k/g_v (f16).
// MODE 1: out = attn @ w_proj + bias (f32).
// ---------------------------------------------------------------------------
#define TSH 40
#define STG_H (128 * TSH)          // halves per operand stage
#define STG_B (STG_H * 2)          // bytes per operand stage
#define NSTG 5
#define GEMM_SMEM (NSTG * 2 * STG_B)
#define A_MI 1280                  // 16*TSH*2 bytes between 16-row blocks
#define KS_B 32                    // 16 halves per k16 slice

template <int MODE>
__global__ __launch_bounds__(256, 2) void gemm_f16(const float* __restrict__ bias,
                                                   float* __restrict__ out) {
    extern __shared__ __half smh[];

    const int tid = threadIdx.x;
    const int bx = blockIdx.x, by = blockIdx.y;
    const int lane = tid & 31, warp = tid >> 5;
    const int wm = warp & 3, wn = warp >> 2;
    const int r = lane >> 2, q = lane & 3;
    const int lrow = lane & 15, lcol = (lane >> 4) * 8;

    const uint32_t sA = (uint32_t)__cvta_generic_to_shared(smh);
    const uint32_t aBase = sA + ((wm * 32 + lrow) * TSH + lcol) * 2;
    const uint32_t bBase = sA + NSTG * STG_B + ((wn * 64 + lrow) * TSH + lcol) * 2;

    float acc[2][8][4];
#pragma unroll
    for (int mi = 0; mi < 2; mi++)
#pragma unroll
        for (int ni = 0; ni < 8; ni++)
#pragma unroll
            for (int c = 0; c < 4; c++) acc[mi][ni][c] = 0.f;

    const int srow = tid >> 1, soff = (tid & 1) * 16;
    const __half* Ap = (MODE == 0) ? g_x : g_attn;
    const __half* Bp = (MODE == 0) ? g_wqkvT : g_wprojT;
    const __half* Ag = Ap + (size_t)(by * 128 + srow) * 1024 + soff;
    const __half* Bg = Bp + (size_t)(bx * 128 + srow) * 1024 + soff;
    __half* AsW = smh + srow * TSH + soff;
    __half* BsW = smh + NSTG * STG_H + srow * TSH + soff;

    auto load_stage = [&](int st, int it) {
        const int k0 = it * 32;
#pragma unroll
        for (int l = 0; l < 2; l++) {
            cp16(AsW + st * STG_H + l * 8, Ag + k0 + l * 8);
            cp16(BsW + st * STG_H + l * 8, Bg + k0 + l * 8);
        }
        cp_commit();
    };

    load_stage(0, 0);
    load_stage(1, 1);
    load_stage(2, 2);
    load_stage(3, 3);
    cp_wait<2>();
    __syncthreads();

    uint32_t fa0[2][4], fa1[2][4], fb0[4][4], fb1[4][4];
    // frags for slice (it=0, ks=0)
#pragma unroll
    for (int mi = 0; mi < 2; mi++) ldm4a(fa0[mi], aBase + mi * A_MI);
#pragma unroll
    for (int nb = 0; nb < 4; nb++) ldm4a(fb0[nb], bBase + nb * A_MI);

    int cs = 0, ns = 1, ls = 4;  // current, next, load stage indices
    for (int it = 0; it < 32; it++) {
        if (it + 4 < 32) load_stage(ls, it + 4);

        const uint32_t aCur = aBase + cs * STG_B;
        const uint32_t bCur = bBase + cs * STG_B;

        // prefetch slice 1 frags, then MMA slice 0
#pragma unroll
        for (int mi = 0; mi < 2; mi++) ldm4a(fa1[mi], aCur + mi * A_MI + KS_B);
#pragma unroll
        for (int nb = 0; nb < 4; nb++) ldm4a(fb1[nb], bCur + nb * A_MI + KS_B);
#pragma unroll
        for (int mi = 0; mi < 2; mi++)
#pragma unroll
            for (int nb = 0; nb < 4; nb++) {
                mma16(acc[mi][2 * nb], fa0[mi], fb0[nb][0], fb0[nb][2]);
                mma16(acc[mi][2 * nb + 1], fa0[mi], fb0[nb][1], fb0[nb][3]);
            }

        // prefetch next stage slice 0 frags, then MMA slice 1
        if (it + 1 < 32) {
            const uint32_t aNx = aBase + ns * STG_B;
            const uint32_t bNx = bBase + ns * STG_B;
#pragma unroll
            for (int mi = 0; mi < 2; mi++) ldm4a(fa0[mi], aNx + mi * A_MI);
#pragma unroll
            for (int nb = 0; nb < 4; nb++) ldm4a(fb0[nb], bNx + nb * A_MI);
        }
#pragma unroll
        for (int mi = 0; mi < 2; mi++)
#pragma unroll
            for (int nb = 0; nb < 4; nb++) {
                mma16(acc[mi][2 * nb], fa1[mi], fb1[nb][0], fb1[nb][2]);
                mma16(acc[mi][2 * nb + 1], fa1[mi], fb1[nb][1], fb1[nb][3]);
            }

        if (it < 28) cp_wait<2>(); else cp_wait<0>();
        __syncthreads();

        cs = ns;
        ns = (ns == NSTG - 1) ? 0 : ns + 1;
        ls = (ls == NSTG - 1) ? 0 : ls + 1;
    }

    // Epilogue: C frag (mi,ni): rows r / r+8, cols ni*8 + 2q, 2q+1.
#pragma unroll
    for (int mi = 0; mi < 2; mi++)
#pragma unroll
        for (int ni = 0; ni < 8; ni++)
#pragma unroll
            for (int ch = 0; ch < 2; ch++) {
                int gr = by * 128 + wm * 32 + mi * 16 + ch * 8 + r;
                int gc = bx * 128 + wn * 64 + ni * 8 + 2 * q;
                float v1 = acc[mi][ni][ch * 2], v2 = acc[mi][ni][ch * 2 + 1];
                if (MODE == 1) {
                    float2 o = make_float2(v1 + bias[gc], v2 + bias[gc + 1]);
                    *(float2*)&out[(size_t)gr * 1024 + gc] = o;
                } else {
                    int b = gr >> 10, n = gr & 1023;
                    int which = gc >> 10, within = gc & 1023;
                    int h = within >> 6, d = within & 63;
                    size_t idx = (((size_t)(b * HH + h)) * NN + n) * DD + d;
                    if (which == 2) {
                        __half2 o = __floats2half2_rn(v1, v2);
                        *(__half2*)&g_v[idx] = o;
                    } else {
                        int p = d >> 1;
                        float omega = exp2f(-0.41524101186f * (float)p);
                        float ang = (float)n * omega;
                        float si, co;
                        sincosf(ang, &si, &co);
                        __half2 o = __floats2half2_rn(v1 * co - v2 * si,
                                                      v2 * co + v1 * si);
                        __half* dst = which ? g_k : g_q;
                        *(__half2*)&dst[idx] = o;
                    }
                }
            }
}

// ---------------------------------------------------------------------------
// fp16 mma.sync flash attention. CTA = 128 q-rows of one (b,h).
// Warp = 16 q-rows x all 64 keys; quad-local softmax sums; S-acc -> P A-frag
// in registers (no P smem). K: ldmatrix; V: ldmatrix.trans. 3-stage KV ring.
// ---------------------------------------------------------------------------
#define QS_H (128 * 72)
#define KV_H (64 * 72)
#define ATTN_SMEM ((QS_H + 6 * KV_H) * 2)

__global__ __launch_bounds__(256, 2) void attn_f16() {
    extern __shared__ __half smh[];
    __half* Qs = smh;
    __half* Ks = smh + QS_H;
    __half* Vs = smh + QS_H + 3 * KV_H;

    const int tid = threadIdx.x;
    const int lane = tid & 31, w = tid >> 5;
    const int r = lane >> 2, q = lane & 3;
    const int lrow = lane & 15, lcol = (lane >> 4) * 8;
    const int qt = blockIdx.x, h = blockIdx.y, b = blockIdx.z;

    const __half* Qg = g_q + ((size_t)(b * HH + h) * NN + qt * 128) * DD;
    const __half* Kg = g_k + (size_t)(b * HH + h) * NN * DD;
    const __half* Vg = g_v + (size_t)(b * HH + h) * NN * DD;

    auto load_kv = [&](int kt, int st) {
#pragma unroll
        for (int l = 0; l < 2; l++) {
            int c = tid + 256 * l;
            int row = c >> 3, ch = c & 7;
            cp16(&Ks[st * KV_H + row * 72 + ch * 8],
                 Kg + (size_t)(kt * 64 + row) * DD + ch * 8);
            cp16(&Vs[st * KV_H + row * 72 + ch * 8],
                 Vg + (size_t)(kt * 64 + row) * DD + ch * 8);
        }
        cp_commit();
    };

#pragma unroll
    for (int l = 0; l < 4; l++) {
        int c = tid + 256 * l;
        int row = c >> 3, ch = c & 7;
        cp16(&Qs[row * 72 + ch * 8], Qg + (size_t)row * DD + ch * 8);
    }
    load_kv(0, 0);
    load_kv(1, 1);

    uint32_t qf[4][4];
    float Oa[8][4];
#pragma unroll
    for (int ni = 0; ni < 8; ni++)
#pragma unroll
        for (int c = 0; c < 4; c++) Oa[ni][c] = 0.f;
    float lsum0 = 0.f, lsum1 = 0.f;

    for (int kt = 0; kt < 16; kt++) {
        cp_wait<1>();
        __syncthreads();
        if (kt == 0) {
#pragma unroll
            for (int j = 0; j < 4; j++)
                ldm4(qf[j], &Qs[(w * 16 + lrow) * 72 + j * 16 + lcol]);
        }
        if (kt + 2 < 16) load_kv(kt + 2, (kt + 2) % 3);

        const __half* Kc = Ks + (kt % 3) * KV_H;
        const __half* Vc = Vs + (kt % 3) * KV_H;

        float s[8][4];
#pragma unroll
        for (int ni = 0; ni < 8; ni++)
#pragma unroll
            for (int c = 0; c < 4; c++) s[ni][c] = 0.f;
#pragma unroll
        for (int j = 0; j < 4; j++) {
            uint32_t kf[4][4];
#pragma unroll
            for (int nb = 0; nb < 4; nb++)
                ldm4(kf[nb], &Kc[(nb * 16 + lrow) * 72 + j * 16 + lcol]);
#pragma unroll
            for (int nb = 0; nb < 4; nb++) {
                mma16(s[2 * nb], qf[j], kf[nb][0], kf[nb][2]);
                mma16(s[2 * nb + 1], qf[j], kf[nb][1], kf[nb][3]);
            }
        }

        float rs0 = 0.f, rs1 = 0.f;
#pragma unroll
        for (int j = 0; j < 4; j++) {
            float e00 = __expf(s[2 * j][0] * 0.125f);
            float e01 = __expf(s[2 * j][1] * 0.125f);
            float e02 = __expf(s[2 * j][2] * 0.125f);
            float e03 = __expf(s[2 * j][3] * 0.125f);
            float e10 = __expf(s[2 * j + 1][0] * 0.125f);
            float e11 = __expf(s[2 * j + 1][1] * 0.125f);
            float e12 = __expf(s[2 * j + 1][2] * 0.125f);
            float e13 = __expf(s[2 * j + 1][3] * 0.125f);
            rs0 += e00 + e01 + e10 + e11;
            rs1 += e02 + e03 + e12 + e13;
            uint32_t pa[4];
            pa[0] = packh2(e00, e01);
            pa[1] = packh2(e02, e03);
            pa[2] = packh2(e10, e11);
            pa[3] = packh2(e12, e13);

            uint32_t vf[4][4];
#pragma unroll
            for (int g = 0; g < 4; g++)
                ldm4t(vf[g], &Vc[(j * 16 + lrow) * 72 + g * 16 + lcol]);
#pragma unroll
            for (int g = 0; g < 4; g++) {
                mma16(Oa[2 * g], pa, vf[g][0], vf[g][1]);
                mma16(Oa[2 * g + 1], pa, vf[g][2], vf[g][3]);
            }
        }
        rs0 += __shfl_xor_sync(0xffffffffu, rs0, 1);
        rs0 += __shfl_xor_sync(0xffffffffu, rs0, 2);
        rs1 += __shfl_xor_sync(0xffffffffu, rs1, 1);
        rs1 += __shfl_xor_sync(0xffffffffu, rs1, 2);
        lsum0 += rs0;
        lsum1 += rs1;
        __syncthreads();
    }

    float inv0 = 1.f / lsum0, inv1 = 1.f / lsum1;
    int n0 = qt * 128 + w * 16 + r;
    size_t b0 = (((size_t)(b * NN + n0)) * HH + h) * DD;
    size_t b1 = (((size_t)(b * NN + n0 + 8)) * HH + h) * DD;
#pragma unroll
    for (int ni = 0; ni < 8; ni++) {
        *(__half2*)&g_attn[b0 + ni * 8 + 2 * q] =
            __floats2half2_rn(Oa[ni][0] * inv0, Oa[ni][1] * inv0);
        *(__half2*)&g_attn[b1 + ni * 8 + 2 * q] =
            __floats2half2_rn(Oa[ni][2] * inv1, Oa[ni][3] * inv1);
    }
}

extern "C" void kernel_launch(void* const* d_in, const int* in_sizes, int n_in,
                              void* d_out, int out_size) {
    const float* x = (const float*)d_in[0];
    const float* w_qkv = (const float*)d_in[1];
    const float* w_proj = (const float*)d_in[2];
    const float* b_proj = (const float*)d_in[3];
    float* out = (float*)d_out;

    cudaFuncSetAttribute(gemm_f16<0>, cudaFuncAttributeMaxDynamicSharedMemorySize,
                         GEMM_SMEM);
    cudaFuncSetAttribute(gemm_f16<1>, cudaFuncAttributeMaxDynamicSharedMemorySize,
                         GEMM_SMEM);
    cudaFuncSetAttribute(attn_f16, cudaFuncAttributeMaxDynamicSharedMemorySize,
                         ATTN_SMEM);

    __half* gx;  cudaGetSymbolAddress((void**)&gx, g_x);
    __half* gwq; cudaGetSymbolAddress((void**)&gwq, g_wqkvT);
    __half* gwp; cudaGetSymbolAddress((void**)&gwp, g_wprojT);

    conv_x<<<8192, 256>>>(x, gx);
    tconv<<<dim3(96, 32), 256>>>(w_qkv, gwq, 3072);
    tconv<<<dim3(32, 32), 256>>>(w_proj, gwp, 1024);

    gemm_f16<0><<<dim3(24, 64), 256, GEMM_SMEM>>>(nullptr, nullptr);
    attn_f16<<<dim3(8, 16, 8), 256, ATTN_SMEM>>>();
    gemm_f16<1><<<dim3(8, 64), 256, GEMM_SMEM>>>(b_proj, out);
}